// round 4
// baseline (speedup 1.0000x reference)
#include <cuda_runtime.h>
#include <cstdint>

// Problem constants
#define N_INN   50000
#define NC      64
#define NT      8
#define NE      800000
#define N_OUTN  50000
#define NF      64
#define KD      512   // NT*NC

// ---------------- scratch (static device allocations only) ----------------
static __device__ int    g_count[N_OUTN];
static __device__ int    g_offset[N_OUTN + 1];
static __device__ int    g_cursor[N_OUTN];
static __device__ int    g_in_sorted[NE];
static __device__ float4 g_ef_sorted[NE * 2];                 // 8 floats / edge, sorted order
static __device__ float4 g_agg[(size_t)N_OUTN * (KD / 4)];    // 50000 x 512 fp32 = 102.4 MB

__device__ __forceinline__ int clampi(int v, int hi) {
    v = v < 0 ? 0 : v;
    return v >= hi ? hi - 1 : v;
}

// ---------------- k1: zero histogram ----------------
__global__ void k_zero() {
    int i = blockIdx.x * blockDim.x + threadIdx.x;
    if (i < N_OUTN) g_count[i] = 0;
}

// ---------------- k2: histogram of output node ids (indices are INT32) ----------------
__global__ void k_hist(const int* __restrict__ idx) {
    int e = blockIdx.x * blockDim.x + threadIdx.x;
    if (e < NE) {
        int o = clampi(idx[2 * e], N_OUTN);
        atomicAdd(&g_count[o], 1);
    }
}

// ---------------- k3: single-block exclusive scan (50000 elems) ----------------
__global__ void k_scan() {
    __shared__ int ssum[1024];
    int tid = threadIdx.x;
    const int CH = (N_OUTN + 1023) / 1024;   // 49
    int base = tid * CH;
    int s = 0;
    for (int i = 0; i < CH; i++) {
        int j = base + i;
        if (j < N_OUTN) s += g_count[j];
    }
    ssum[tid] = s;
    __syncthreads();
    // Hillis-Steele inclusive scan over 1024 partials
    for (int off = 1; off < 1024; off <<= 1) {
        int v = (tid >= off) ? ssum[tid - off] : 0;
        __syncthreads();
        ssum[tid] += v;
        __syncthreads();
    }
    int run = ssum[tid] - s;   // exclusive prefix for this thread's chunk
    for (int i = 0; i < CH; i++) {
        int j = base + i;
        if (j < N_OUTN) {
            g_offset[j] = run;
            g_cursor[j] = run;
            run += g_count[j];
        }
    }
    if (tid == 0) g_offset[N_OUTN] = NE;
}

// ---------------- k4: permute edges into segment-sorted order ----------------
__global__ void k_permute(const int* __restrict__ idx,
                          const float* __restrict__ ef) {
    int e = blockIdx.x * blockDim.x + threadIdx.x;
    if (e >= NE) return;
    int o  = clampi(idx[2 * e],     N_OUTN);
    int in = clampi(idx[2 * e + 1], N_INN);
    int pos = atomicAdd(&g_cursor[o], 1);
    pos = clampi(pos, NE);
    g_in_sorted[pos] = in;
    float4 v0, v1;
    v0.x = ef[0 * NE + e]; v0.y = ef[1 * NE + e];
    v0.z = ef[2 * NE + e]; v0.w = ef[3 * NE + e];
    v1.x = ef[4 * NE + e]; v1.y = ef[5 * NE + e];
    v1.z = ef[6 * NE + e]; v1.w = ef[7 * NE + e];
    g_ef_sorted[pos * 2]     = v0;
    g_ef_sorted[pos * 2 + 1] = v1;
}

// ---------------- k5: per-output-node aggregation (one warp / node) ----------------
__device__ __forceinline__ void fma16(float acc[16], float4 e0, float4 e1,
                                      float a0, float a1) {
    acc[0]  += e0.x * a0;  acc[1]  += e0.x * a1;
    acc[2]  += e0.y * a0;  acc[3]  += e0.y * a1;
    acc[4]  += e0.z * a0;  acc[5]  += e0.z * a1;
    acc[6]  += e0.w * a0;  acc[7]  += e0.w * a1;
    acc[8]  += e1.x * a0;  acc[9]  += e1.x * a1;
    acc[10] += e1.y * a0;  acc[11] += e1.y * a1;
    acc[12] += e1.z * a0;  acc[13] += e1.z * a1;
    acc[14] += e1.w * a0;  acc[15] += e1.w * a1;
}

__global__ __launch_bounds__(256) void k_agg(const float* __restrict__ nf) {
    int gw   = (blockIdx.x * blockDim.x + threadIdx.x) >> 5;
    int lane = threadIdx.x & 31;
    if (gw >= N_OUTN) return;
    int start = g_offset[gw];
    int end   = g_offset[gw + 1];

    float acc[16];
#pragma unroll
    for (int i = 0; i < 16; i++) acc[i] = 0.f;

    int p = start;
    // unroll-by-2 for memory-level parallelism (L2-latency chains)
    for (; p + 2 <= end; p += 2) {
        int in0 = g_in_sorted[p];
        int in1 = g_in_sorted[p + 1];
        float4 e00 = g_ef_sorted[p * 2];
        float4 e01 = g_ef_sorted[p * 2 + 1];
        float4 e10 = g_ef_sorted[p * 2 + 2];
        float4 e11 = g_ef_sorted[p * 2 + 3];
        float a00 = nf[in0 * NC + lane];
        float a01 = nf[in0 * NC + 32 + lane];
        float a10 = nf[in1 * NC + lane];
        float a11 = nf[in1 * NC + 32 + lane];
        fma16(acc, e00, e01, a00, a01);
        fma16(acc, e10, e11, a10, a11);
    }
    if (p < end) {
        int in0 = g_in_sorted[p];
        float4 e00 = g_ef_sorted[p * 2];
        float4 e01 = g_ef_sorted[p * 2 + 1];
        float a00 = nf[in0 * NC + lane];
        float a01 = nf[in0 * NC + 32 + lane];
        fma16(acc, e00, e01, a00, a01);
    }

    float* dst = (float*)g_agg + (size_t)gw * KD;
#pragma unroll
    for (int t = 0; t < 8; t++) {
        dst[t * 64 + lane]      = acc[2 * t];
        dst[t * 64 + 32 + lane] = acc[2 * t + 1];
    }
}

// ---------------- k6: SGEMM  out(50000x64) = Agg(50000x512) @ Kmat(512x64) + bias ----------------
// BM=128, BN=64 (full N), BK=32; 128 threads; 8x8 microtile per thread.
__global__ __launch_bounds__(128) void k_gemm(const float* __restrict__ Kmat,
                                              const float* __restrict__ bias,
                                              float* __restrict__ out) {
    __shared__ float As[32][132];   // [k][m], padded row (528B, 16B-aligned)
    __shared__ float Bs[32][64];    // [k][n]

    int tid = threadIdx.x;
    int m0  = blockIdx.x * 128;
    int tm  = (tid & 15) * 8;       // 0..120
    int tn  = (tid >> 4) * 8;       // 0..56

    float acc[8][8];
#pragma unroll
    for (int i = 0; i < 8; i++)
#pragma unroll
        for (int j = 0; j < 8; j++) acc[i][j] = 0.f;

    const float* aggf = (const float*)g_agg;

    for (int k0 = 0; k0 < KD; k0 += 32) {
        // Load A tile: thread tid owns global row m0+tid, all 32 k's (8 x float4)
        {
            int gm = m0 + tid;
            bool vld = (gm < N_OUTN);
            const float* src = aggf + (size_t)gm * KD + k0;
#pragma unroll
            for (int i = 0; i < 8; i++) {
                float4 v = vld ? *(const float4*)(src + i * 4)
                               : make_float4(0.f, 0.f, 0.f, 0.f);
                As[i * 4 + 0][tid] = v.x;
                As[i * 4 + 1][tid] = v.y;
                As[i * 4 + 2][tid] = v.z;
                As[i * 4 + 3][tid] = v.w;
            }
        }
        // Load B tile: 32x64 floats = 512 float4 / 128 threads = 4 each (coalesced)
        {
#pragma unroll
            for (int i = 0; i < 4; i++) {
                int idx = tid + i * 128;
                int n4 = idx & 15;
                int kk = idx >> 4;
                float4 v = *(const float4*)(Kmat + (size_t)(k0 + kk) * 64 + n4 * 4);
                *(float4*)&Bs[kk][n4 * 4] = v;
            }
        }
        __syncthreads();

#pragma unroll
        for (int k = 0; k < 32; k++) {
            float a[8], b[8];
#pragma unroll
            for (int i = 0; i < 8; i++) a[i] = As[k][tm + i];
#pragma unroll
            for (int j = 0; j < 8; j++) b[j] = Bs[k][tn + j];
#pragma unroll
            for (int i = 0; i < 8; i++)
#pragma unroll
                for (int j = 0; j < 8; j++)
                    acc[i][j] += a[i] * b[j];
        }
        __syncthreads();
    }

    // Epilogue: + bias, write out
    float bv[8];
#pragma unroll
    for (int j = 0; j < 8; j++) bv[j] = bias[tn + j];

#pragma unroll
    for (int i = 0; i < 8; i++) {
        int gm = m0 + tm + i;
        if (gm < N_OUTN) {
#pragma unroll
            for (int j = 0; j < 8; j += 4) {
                float4 v;
                v.x = acc[i][j + 0] + bv[j + 0];
                v.y = acc[i][j + 1] + bv[j + 1];
                v.z = acc[i][j + 2] + bv[j + 2];
                v.w = acc[i][j + 3] + bv[j + 3];
                *(float4*)(out + (size_t)gm * NF + tn + j) = v;
            }
        }
    }
}

// ---------------- launch ----------------
extern "C" void kernel_launch(void* const* d_in, const int* in_sizes, int n_in,
                              void* d_out, int out_size) {
    const float* nf   = (const float*)d_in[0];   // node_features (50000,64)
    const float* ef   = (const float*)d_in[1];   // edge_features (8,800000)
    const int*   idx  = (const int*)d_in[2];     // indices (800000,2) — int32 (JAX x64 disabled)
    const float* Kmat = (const float*)d_in[3];   // kernel (8,64,64)
    const float* bias = (const float*)d_in[4];   // bias (64,)
    float*       out  = (float*)d_out;           // (50000,64)

    k_zero   <<<(N_OUTN + 255) / 256, 256>>>();
    k_hist   <<<(NE + 255) / 256, 256>>>(idx);
    k_scan   <<<1, 1024>>>();
    k_permute<<<(NE + 255) / 256, 256>>>(idx, ef);
    k_agg    <<<(N_OUTN * 32 + 255) / 256, 256>>>(nf);
    k_gemm   <<<(N_OUTN + 127) / 128, 128>>>(Kmat, bias, out);
}

// round 5
// speedup vs baseline: 2.7831x; 2.7831x over previous
#include <cuda_runtime.h>
#include <cstdint>

// Problem constants
#define N_INN   50000
#define NC      64
#define NT      8
#define NE      800000
#define N_OUTN  50000
#define NF      64
#define KD      512   // NT*NC
#define NBLK_SCAN 196 // ceil(50000/256)

// ---------------- scratch (static device allocations only) ----------------
static __device__ int    g_count[N_OUTN];
static __device__ int    g_offset[N_OUTN + 1];
static __device__ int    g_cursor[N_OUTN];
static __device__ int    g_bsum[NBLK_SCAN];
static __device__ int    g_in_sorted[NE];
static __device__ float4 g_ef_sorted[NE * 2];                 // 8 floats / edge, sorted order
static __device__ float4 g_agg[(size_t)N_OUTN * (KD / 4)];    // 50000 x 512 fp32 = 102.4 MB

__device__ __forceinline__ int clampi(int v, int hi) {
    v = v < 0 ? 0 : v;
    return v >= hi ? hi - 1 : v;
}

__device__ __forceinline__ uint32_t f2tf32(float f) {
    uint32_t u;
    asm("cvt.rna.tf32.f32 %0, %1;" : "=r"(u) : "f"(f));
    return u;
}

// ---------------- k1: zero histogram ----------------
__global__ void k_zero() {
    int i = blockIdx.x * blockDim.x + threadIdx.x;
    if (i < N_OUTN) g_count[i] = 0;
}

// ---------------- k2: histogram of output node ids (indices are INT32) ----------------
__global__ void k_hist(const int* __restrict__ idx) {
    int e = blockIdx.x * blockDim.x + threadIdx.x;
    if (e < NE) {
        int o = clampi(idx[2 * e], N_OUTN);
        atomicAdd(&g_count[o], 1);
    }
}

// ---------------- parallel coalesced exclusive scan (3 kernels) ----------------
__device__ __forceinline__ int block_scan_excl(int v, int* wsum, int* block_total) {
    int tid = threadIdx.x, lane = tid & 31, wid = tid >> 5;
    int x = v;
#pragma unroll
    for (int off = 1; off < 32; off <<= 1) {
        int y = __shfl_up_sync(0xffffffffu, x, off);
        if (lane >= off) x += y;
    }
    if (lane == 31) wsum[wid] = x;
    __syncthreads();
    if (tid == 0) {
        int run = 0;
#pragma unroll
        for (int j = 0; j < 8; j++) { int t = wsum[j]; wsum[j] = run; run += t; }
        *block_total = run;
    }
    __syncthreads();
    return x - v + wsum[wid];
}

__global__ void k_scan_a() {
    __shared__ int wsum[8];
    __shared__ int btot;
    int i = blockIdx.x * 256 + threadIdx.x;
    int v = (i < N_OUTN) ? g_count[i] : 0;
    int excl = block_scan_excl(v, wsum, &btot);
    if (i < N_OUTN) g_offset[i] = excl;
    if (threadIdx.x == 0) g_bsum[blockIdx.x] = btot;
}

__global__ void k_scan_b() {
    __shared__ int wsum[8];
    __shared__ int btot;
    int tid = threadIdx.x;
    int v = (tid < NBLK_SCAN) ? g_bsum[tid] : 0;
    int excl = block_scan_excl(v, wsum, &btot);
    if (tid < NBLK_SCAN) g_bsum[tid] = excl;
}

__global__ void k_scan_c() {
    int i = blockIdx.x * 256 + threadIdx.x;
    if (i < N_OUTN) {
        int v = g_offset[i] + g_bsum[blockIdx.x];
        g_offset[i] = v;
        g_cursor[i] = v;
    }
    if (i == 0) g_offset[N_OUTN] = NE;
}

// ---------------- k4: permute edges into segment-sorted order ----------------
__global__ void k_permute(const int* __restrict__ idx,
                          const float* __restrict__ ef) {
    int e = blockIdx.x * blockDim.x + threadIdx.x;
    if (e >= NE) return;
    int o  = clampi(idx[2 * e],     N_OUTN);
    int in = clampi(idx[2 * e + 1], N_INN);
    int pos = atomicAdd(&g_cursor[o], 1);
    pos = clampi(pos, NE);
    g_in_sorted[pos] = in;
    float4 v0, v1;
    v0.x = ef[0 * NE + e]; v0.y = ef[1 * NE + e];
    v0.z = ef[2 * NE + e]; v0.w = ef[3 * NE + e];
    v1.x = ef[4 * NE + e]; v1.y = ef[5 * NE + e];
    v1.z = ef[6 * NE + e]; v1.w = ef[7 * NE + e];
    g_ef_sorted[pos * 2]     = v0;
    g_ef_sorted[pos * 2 + 1] = v1;
}

// ---------------- k5: per-output-node aggregation (one warp / node) ----------------
__device__ __forceinline__ void fma16(float acc[16], float4 e0, float4 e1,
                                      float a0, float a1) {
    acc[0]  += e0.x * a0;  acc[1]  += e0.x * a1;
    acc[2]  += e0.y * a0;  acc[3]  += e0.y * a1;
    acc[4]  += e0.z * a0;  acc[5]  += e0.z * a1;
    acc[6]  += e0.w * a0;  acc[7]  += e0.w * a1;
    acc[8]  += e1.x * a0;  acc[9]  += e1.x * a1;
    acc[10] += e1.y * a0;  acc[11] += e1.y * a1;
    acc[12] += e1.z * a0;  acc[13] += e1.z * a1;
    acc[14] += e1.w * a0;  acc[15] += e1.w * a1;
}

__global__ __launch_bounds__(256) void k_agg(const float* __restrict__ nf) {
    int gw   = (blockIdx.x * blockDim.x + threadIdx.x) >> 5;
    int lane = threadIdx.x & 31;
    if (gw >= N_OUTN) return;
    int start = g_offset[gw];
    int end   = g_offset[gw + 1];

    float acc[16];
#pragma unroll
    for (int i = 0; i < 16; i++) acc[i] = 0.f;

    int p = start;
    for (; p + 2 <= end; p += 2) {
        int in0 = g_in_sorted[p];
        int in1 = g_in_sorted[p + 1];
        float4 e00 = g_ef_sorted[p * 2];
        float4 e01 = g_ef_sorted[p * 2 + 1];
        float4 e10 = g_ef_sorted[p * 2 + 2];
        float4 e11 = g_ef_sorted[p * 2 + 3];
        float a00 = nf[in0 * NC + lane];
        float a01 = nf[in0 * NC + 32 + lane];
        float a10 = nf[in1 * NC + lane];
        float a11 = nf[in1 * NC + 32 + lane];
        fma16(acc, e00, e01, a00, a01);
        fma16(acc, e10, e11, a10, a11);
    }
    if (p < end) {
        int in0 = g_in_sorted[p];
        float4 e00 = g_ef_sorted[p * 2];
        float4 e01 = g_ef_sorted[p * 2 + 1];
        float a00 = nf[in0 * NC + lane];
        float a01 = nf[in0 * NC + 32 + lane];
        fma16(acc, e00, e01, a00, a01);
    }

    float* dst = (float*)g_agg + (size_t)gw * KD;
#pragma unroll
    for (int t = 0; t < 8; t++) {
        dst[t * 64 + lane]      = acc[2 * t];
        dst[t * 64 + 32 + lane] = acc[2 * t + 1];
    }
}

// ---------------- k6: TF32 tensor-core GEMM ----------------
// out(50000x64) = Agg(50000x512) @ Kmat(512x64) + bias
// Block: 128 threads (4 warps). BM=64 (16/warp), BN=64 (full), BK=32.
// mma.sync.m16n8k8.tf32, fp32 accumulate. tf32-converted in smem.
// As stride 36: frag bank = 4*gid + tig  (bijection, conflict-free)
// Bs stride 72: frag bank = 8*tig + gid  (bijection, conflict-free)
__global__ __launch_bounds__(128) void k_gemm_tf32(const float* __restrict__ Kmat,
                                                   const float* __restrict__ bias,
                                                   float* __restrict__ out) {
    __shared__ uint32_t As[64][36];   // [m][k], tf32 bits
    __shared__ uint32_t Bs[32][72];   // [k][n], tf32 bits

    int tid  = threadIdx.x;
    int warp = tid >> 5;
    int lane = tid & 31;
    int gid  = lane >> 2;     // group id 0..7
    int tig  = lane & 3;      // thread-in-group 0..3
    int m0   = blockIdx.x * 64;

    float acc[8][4];
#pragma unroll
    for (int nt = 0; nt < 8; nt++)
#pragma unroll
        for (int j = 0; j < 4; j++) acc[nt][j] = 0.f;

    const float* aggf = (const float*)g_agg;

    for (int k0 = 0; k0 < KD; k0 += 32) {
        // Stage A tile 64x32: 512 float4 / 128 threads = 4 each
#pragma unroll
        for (int i = 0; i < 4; i++) {
            int fi  = tid + i * 128;
            int row = fi >> 3;          // 0..63
            int c4  = fi & 7;           // 0..7
            int gm  = m0 + row;
            float4 v = (gm < N_OUTN)
                     ? *(const float4*)(aggf + (size_t)gm * KD + k0 + c4 * 4)
                     : make_float4(0.f, 0.f, 0.f, 0.f);
            As[row][c4 * 4 + 0] = f2tf32(v.x);
            As[row][c4 * 4 + 1] = f2tf32(v.y);
            As[row][c4 * 4 + 2] = f2tf32(v.z);
            As[row][c4 * 4 + 3] = f2tf32(v.w);
        }
        // Stage B tile 32x64: 512 float4 / 128 threads = 4 each
#pragma unroll
        for (int i = 0; i < 4; i++) {
            int fi = tid + i * 128;
            int kk = fi >> 4;           // 0..31
            int n4 = fi & 15;           // 0..15
            float4 v = *(const float4*)(Kmat + (size_t)(k0 + kk) * 64 + n4 * 4);
            Bs[kk][n4 * 4 + 0] = f2tf32(v.x);
            Bs[kk][n4 * 4 + 1] = f2tf32(v.y);
            Bs[kk][n4 * 4 + 2] = f2tf32(v.z);
            Bs[kk][n4 * 4 + 3] = f2tf32(v.w);
        }
        __syncthreads();

#pragma unroll
        for (int kk = 0; kk < 32; kk += 8) {
            int wm = warp * 16;
            uint32_t a0 = As[wm + gid][kk + tig];
            uint32_t a1 = As[wm + gid + 8][kk + tig];
            uint32_t a2 = As[wm + gid][kk + tig + 4];
            uint32_t a3 = As[wm + gid + 8][kk + tig + 4];
#pragma unroll
            for (int nt = 0; nt < 8; nt++) {
                uint32_t b0 = Bs[kk + tig][nt * 8 + gid];
                uint32_t b1 = Bs[kk + tig + 4][nt * 8 + gid];
                asm volatile(
                    "mma.sync.aligned.m16n8k8.row.col.f32.tf32.tf32.f32 "
                    "{%0,%1,%2,%3}, {%4,%5,%6,%7}, {%8,%9}, {%0,%1,%2,%3};\n"
                    : "+f"(acc[nt][0]), "+f"(acc[nt][1]),
                      "+f"(acc[nt][2]), "+f"(acc[nt][3])
                    : "r"(a0), "r"(a1), "r"(a2), "r"(a3), "r"(b0), "r"(b1));
            }
        }
        __syncthreads();
    }

    // Epilogue: c0,c1 -> row m0+warp*16+gid, cols nt*8+tig*2+{0,1}
    //           c2,c3 -> row +8
    int mA = m0 + warp * 16 + gid;
    int mB = mA + 8;
#pragma unroll
    for (int nt = 0; nt < 8; nt++) {
        int n = nt * 8 + tig * 2;
        float b0 = bias[n], b1 = bias[n + 1];
        if (mA < N_OUTN) {
            float2 v; v.x = acc[nt][0] + b0; v.y = acc[nt][1] + b1;
            *(float2*)(out + (size_t)mA * NF + n) = v;
        }
        if (mB < N_OUTN) {
            float2 v; v.x = acc[nt][2] + b0; v.y = acc[nt][3] + b1;
            *(float2*)(out + (size_t)mB * NF + n) = v;
        }
    }
}

// ---------------- launch ----------------
extern "C" void kernel_launch(void* const* d_in, const int* in_sizes, int n_in,
                              void* d_out, int out_size) {
    const float* nf   = (const float*)d_in[0];   // node_features (50000,64)
    const float* ef   = (const float*)d_in[1];   // edge_features (8,800000)
    const int*   idx  = (const int*)d_in[2];     // indices (800000,2) int32
    const float* Kmat = (const float*)d_in[3];   // kernel (8,64,64)
    const float* bias = (const float*)d_in[4];   // bias (64,)
    float*       out  = (float*)d_out;           // (50000,64)

    k_zero   <<<(N_OUTN + 255) / 256, 256>>>();
    k_hist   <<<(NE + 255) / 256, 256>>>(idx);
    k_scan_a <<<NBLK_SCAN, 256>>>();
    k_scan_b <<<1, 256>>>();
    k_scan_c <<<NBLK_SCAN, 256>>>();
    k_permute<<<(NE + 255) / 256, 256>>>(idx, ef);
    k_agg    <<<(N_OUTN * 32 + 255) / 256, 256>>>(nf);
    k_gemm_tf32<<<(N_OUTN + 63) / 64, 128>>>(Kmat, bias, out);
}